// round 16
// baseline (speedup 1.0000x reference)
#include <cuda_runtime.h>
#include <cuda_bf16.h>
#include <math.h>

// ---------------------------------------------------------------------------
// DRMM matching score, GB300 (sm_103a) — round 16: OCCUPANCY VIA SMALL CTA TILE
//   Model: stall-bound (issue 29-33%, nothing saturated; compat HMMA rt~7.5cyc).
//   Lever: warps/SM 12->20 at ~constant instruction count.
//   MT=64 rows/CTA -> smem 42.7KB -> 5 CTAs/SM (launch_bounds(128,5), no spill).
//   B tile prebuilt per batch in gmem (qprep); CTAs copy it (coalesced uint4).
//   Mainloop/epilogue = R14 mt=1 shape (proven); separate reduce (proven).
//   Gating branch dropped: softmax over batch sums to exactly 1.
// ---------------------------------------------------------------------------

#define BB   256
#define QQ   50
#define EE   50
#define DD   2000
#define NB   11
#define QB   (QQ * NB)        // 550
#define MT   64               // d-rows per CTA
#define NTILE 32              // 32*64 = 2048 >= 2000
#define ROWB 336              // bf16 row stride bytes (168 bf16)
#define ROWW 84               // words per row
#define KSTEPS 10             // K=160 / 16
#define NT7  7                // q n-tiles (56 >= 50)
#define BT_W (56 * ROWW)      // 4704 words per batch B tile
#define BT_V (BT_W / 4)       // 1176 uint4

// smem layout
#define SM_B    0             // 56 * 336 = 18816
#define SM_A    18816         // 64 * 336 = 21504 -> 40320
#define SM_HIST 40320         // 550*4 = 2200 -> 42520
#define SM_QV   42520         // 64  -> 42584
#define SM_DV   42584         // 64  -> 42648
#define SM_TOTAL 42688

__device__ uint4 g_btile[(size_t)BB * BT_V];               // prebuilt bf16 B tiles
__device__ unsigned char g_qvg[BB * 64];
__device__ unsigned char g_part[(size_t)NTILE * BB * QB];  // u8 slices
typedef unsigned long long u64;

__device__ __forceinline__ unsigned smem_u32(const void* p) {
    unsigned a;
    asm("{ .reg .u64 t; cvta.to.shared.u64 t, %1; cvt.u32.u64 %0, t; }"
        : "=r"(a) : "l"(p));
    return a;
}
__device__ __forceinline__ void split2(float x0, float x1,
                                       unsigned& hi, unsigned& lo) {
    __nv_bfloat16 h0 = __float2bfloat16(x0);
    __nv_bfloat16 h1 = __float2bfloat16(x1);
    float r0 = x0 - __bfloat162float(h0);
    float r1 = x1 - __bfloat162float(h1);
    __nv_bfloat16 l0 = __float2bfloat16(r0);
    __nv_bfloat16 l1 = __float2bfloat16(r1);
    hi = (unsigned)__bfloat16_as_ushort(h0) | ((unsigned)__bfloat16_as_ushort(h1) << 16);
    lo = (unsigned)__bfloat16_as_ushort(l0) | ((unsigned)__bfloat16_as_ushort(l1) << 16);
}
__device__ __forceinline__ void ldsm4(unsigned addr, unsigned& r0, unsigned& r1,
                                      unsigned& r2, unsigned& r3) {
    asm volatile("ldmatrix.sync.aligned.m8n8.x4.shared.b16 {%0,%1,%2,%3}, [%4];"
                 : "=r"(r0), "=r"(r1), "=r"(r2), "=r"(r3) : "r"(addr));
}
__device__ __forceinline__ void ldsm2(unsigned addr, unsigned& r0, unsigned& r1) {
    asm volatile("ldmatrix.sync.aligned.m8n8.x2.shared.b16 {%0,%1}, [%2];"
                 : "=r"(r0), "=r"(r1) : "r"(addr));
}
__device__ __forceinline__ void mma16816(float* c, const unsigned* a,
                                         unsigned b0, unsigned b1) {
    asm volatile(
        "mma.sync.aligned.m16n8k16.row.col.f32.bf16.bf16.f32 "
        "{%0,%1,%2,%3}, {%4,%5,%6,%7}, {%8,%9}, {%0,%1,%2,%3};"
        : "+f"(c[0]), "+f"(c[1]), "+f"(c[2]), "+f"(c[3])
        : "r"(a[0]), "r"(a[1]), "r"(a[2]), "r"(a[3]), "r"(b0), "r"(b1));
}

// ---------------------------------------------------------------------------
// Pre-kernel: build the bf16-split q tile (rows 0..55) once per batch.
// ---------------------------------------------------------------------------
__global__ void qprep_kernel(const float* __restrict__ qemb,
                             const int*   __restrict__ qids)
{
    const int b = blockIdx.x;
    const int t = threadIdx.x;          // 0..63
    if (t < 56) {
        unsigned* brow = ((unsigned*)g_btile) + (size_t)b * BT_W + t * ROWW;
        if (t < QQ) {
            const float2* src = (const float2*)(qemb + ((size_t)b * QQ + t) * EE);
            float2 v[25];
            float ss = 0.f;
#pragma unroll
            for (int c = 0; c < 25; c++) { v[c] = src[c]; ss += v[c].x * v[c].x + v[c].y * v[c].y; }
            const float r = 1.0f / (sqrtf(ss) + 1e-8f);
#pragma unroll
            for (int c = 0; c < 25; c++) {
                unsigned hi, lo;
                split2(v[c].x * r, v[c].y * r, hi, lo);
                brow[c]      = hi;
                brow[25 + c] = lo;
                brow[50 + c] = hi;
            }
#pragma unroll
            for (int j = 75; j < 84; j++) brow[j] = 0;
        } else {
#pragma unroll
            for (int j = 0; j < 84; j++) brow[j] = 0;
        }
    }
    g_qvg[b * 64 + t] = (t < QQ && qids[b * QQ + t] > 0) ? 1 : 0;
}

// ---------------------------------------------------------------------------
__global__ void __launch_bounds__(128, 5)
simhist_kernel(const float* __restrict__ demb,
               const int*   __restrict__ dids)
{
    extern __shared__ char smem[];
    const unsigned sbase = smem_u32(smem);
    const int b    = blockIdx.y;
    const int tile = blockIdx.x;
    const int tid  = threadIdx.x;
    const int lane = tid & 31;
    const int w    = tid >> 5;          // 0..3

    int* hist_s = (int*)(smem + SM_HIST);
    unsigned char* qv_s = (unsigned char*)(smem + SM_QV);
    unsigned char* dv_s = (unsigned char*)(smem + SM_DV);

    for (int i = tid; i < QB; i += 128) hist_s[i] = 0;

    // ---- staging: threads 0-63 stage A rows; threads 64-127 copy B + flags ----
    if (tid < 64) {
        const int gd  = tile * MT + tid;
        const bool ok = (gd < DD);
        const float2* src = (const float2*)(demb + ((size_t)b * DD + (ok ? gd : 0)) * EE);
        float2 v[25];
        float ss = 0.f;
#pragma unroll
        for (int c = 0; c < 25; c++) {
            float2 x = ok ? src[c] : make_float2(0.f, 0.f);
            v[c] = x;
            ss += x.x * x.x + x.y * x.y;
        }
        const float r = 1.0f / (sqrtf(ss) + 1e-8f);
        dv_s[tid] = (ok && dids[b * DD + (ok ? gd : 0)] > 0) ? 1 : 0;
        unsigned* arow = (unsigned*)(smem + SM_A + tid * ROWB);
#pragma unroll
        for (int c = 0; c < 25; c++) {
            unsigned hi, lo;
            split2(v[c].x * r, v[c].y * r, hi, lo);
            arow[c]      = hi;
            arow[25 + c] = hi;
            arow[50 + c] = lo;
        }
#pragma unroll
        for (int j = 75; j < 84; j++) arow[j] = 0;
    } else {
        const int t2 = tid - 64;
        uint4* bs = (uint4*)(smem + SM_B);
        const uint4* bg = g_btile + (size_t)b * BT_V;
        for (int i = t2; i < BT_V; i += 64) bs[i] = bg[i];
        qv_s[t2] = g_qvg[b * 64 + t2];
    }
    __syncthreads();

    // ---- HMMA mainloop: 4 warps x 16 d-rows (mt = 1) ----
    float acc[NT7][4];
#pragma unroll
    for (int nt = 0; nt < NT7; nt++)
#pragma unroll
        for (int ci = 0; ci < 4; ci++) acc[nt][ci] = 0.f;

    const unsigned aAddr = sbase + SM_A + (unsigned)(w * 16 + (lane & 15)) * ROWB
                         + (unsigned)((lane >> 4) * 16);
    const unsigned bAddr = sbase + SM_B
                         + (unsigned)((lane >> 4) * 8 + (lane & 7)) * ROWB
                         + (unsigned)(((lane >> 3) & 1) * 16);
    const unsigned bAddr2 = sbase + SM_B
                          + (unsigned)(48 + (lane & 7)) * ROWB
                          + (unsigned)(((lane >> 3) & 1) * 16);

#pragma unroll
    for (int ks = 0; ks < KSTEPS; ks++) {
        unsigned am[4];
        ldsm4(aAddr + ks * 32, am[0], am[1], am[2], am[3]);
        unsigned bq[3][4];
#pragma unroll
        for (int p = 0; p < 3; p++)
            ldsm4(bAddr + (unsigned)(p * 16 * ROWB) + ks * 32,
                  bq[p][0], bq[p][1], bq[p][2], bq[p][3]);
        unsigned b6lo, b6hi;
        ldsm2(bAddr2 + ks * 32, b6lo, b6hi);
#pragma unroll
        for (int p = 0; p < 3; p++) {
            mma16816(acc[2 * p],     am, bq[p][0], bq[p][1]);
            mma16816(acc[2 * p + 1], am, bq[p][2], bq[p][3]);
        }
        mma16816(acc[6], am, b6lo, b6hi);
    }

    // ---- epilogue: 2-sample nibble hist + butterfly over 8 lane-groups ----
    const int r0 = w * 16 + (lane >> 2);
    const unsigned dvq = (unsigned)dv_s[r0] | ((unsigned)dv_s[r0 + 8] << 1);
    const int copyidx = lane >> 2;          // 0..7
    const int cbase   = (lane & 3) * 2;

#pragma unroll
    for (int nt = 0; nt < NT7; nt++) {
#pragma unroll
        for (int half = 0; half < 2; half++) {
            const int q = nt * 8 + cbase + half;
            u64 h = 0ull;
            {
                float s0 = acc[nt][half];          // row r0
                float s1 = acc[nt][half + 2];      // row r0 + 8
                int c0 = min(max((int)fmaf(s0, 5.0f, 5.000005f), 0), NB - 1);
                int c1 = min(max((int)fmaf(s1, 5.0f, 5.000005f), 0), NB - 1);
                h += (u64)(dvq & 1u)        << (c0 * 4);
                h += (u64)((dvq >> 1) & 1u) << (c1 * 4);
            }
            u64 he = h & 0x0F0F0F0F0F0F0F0Full;
            u64 ho = (h >> 4) & 0x0F0F0F0F0F0F0F0Full;
#pragma unroll
            for (int o = 4; o < 32; o <<= 1) {
                he += __shfl_xor_sync(0xffffffffu, he, o);
                ho += __shfl_xor_sync(0xffffffffu, ho, o);
            }
            if (((nt * 2 + half) & 7) == copyidx && q < QQ && qv_s[q]) {
#pragma unroll
                for (int bin = 0; bin < NB; bin++) {
                    u64 src = (bin & 1) ? ho : he;
                    int cnt = (int)((src >> ((bin >> 1) * 8)) & 0xFFull);
                    if (cnt) atomicAdd(&hist_s[q * NB + bin], cnt);
                }
            }
        }
    }

    __syncthreads();
    unsigned char* dst = g_part + ((size_t)tile * BB + b) * QB;
    for (int i = tid; i < QB; i += 128) dst[i] = (unsigned char)hist_s[i];
}

// ---------------------------------------------------------------------------
// Reduce: out[b] = b1 + sum_i log(sum_tiles hist + 1e-5) * W1[i]
// ---------------------------------------------------------------------------
__global__ void reduce_kernel(const float* __restrict__ W1,
                              const float* __restrict__ b1,
                              float* __restrict__ out)
{
    const int b = blockIdx.x;
    const int t = threadIdx.x;
    float p = 0.f;
    for (int i = t; i < QB; i += 256) {
        int h = 0;
#pragma unroll
        for (int s = 0; s < NTILE; s++)
            h += (int)g_part[((size_t)s * BB + b) * QB + i];
        p += logf((float)h + 1e-5f) * W1[i];
    }
#pragma unroll
    for (int o = 16; o > 0; o >>= 1) p += __shfl_down_sync(0xffffffffu, p, o);

    __shared__ float red[8];
    if ((t & 31) == 0) red[t >> 5] = p;
    __syncthreads();
    if (t == 0) {
        float s = 0.f;
#pragma unroll
        for (int i = 0; i < 8; i++) s += red[i];
        out[b] = s + b1[0];
    }
}

// ---------------------------------------------------------------------------
extern "C" void kernel_launch(void* const* d_in, const int* in_sizes, int n_in,
                              void* d_out, int out_size)
{
    const float* qemb = (const float*)d_in[0];
    const float* demb = (const float*)d_in[1];
    const float* W1   = (const float*)d_in[2];
    const float* b1   = (const float*)d_in[3];
    const int*   qids = (const int*)d_in[5];
    const int*   dids = (const int*)d_in[6];
    for (int i = 0; i < n_in; i++) {
        switch (in_sizes[i]) {
            case BB * QQ * EE:  qemb = (const float*)d_in[i]; break;
            case BB * DD * EE:  demb = (const float*)d_in[i]; break;
            case QB:            W1   = (const float*)d_in[i]; break;
            case 1:             b1   = (const float*)d_in[i]; break;
            case BB * QQ:       qids = (const int*)d_in[i];   break;
            case BB * DD:       dids = (const int*)d_in[i];   break;
            default: break;     // Wg unused (softmax over batch sums to 1)
        }
    }
    float* out = (float*)d_out;

    static int smem_set = 0;
    if (!smem_set) {
        cudaFuncSetAttribute(simhist_kernel,
                             cudaFuncAttributeMaxDynamicSharedMemorySize, SM_TOTAL);
        smem_set = 1;
    }

    qprep_kernel<<<BB, 64>>>(qemb, qids);
    dim3 grid(NTILE, BB);                         // (32, 256)
    simhist_kernel<<<grid, 128, SM_TOTAL>>>(demb, dids);
    reduce_kernel<<<BB, 256>>>(W1, b1, out);
}

// round 17
// speedup vs baseline: 1.5218x; 1.5218x over previous
#include <cuda_runtime.h>
#include <cuda_bf16.h>
#include <math.h>

// ---------------------------------------------------------------------------
// DRMM matching score, GB300 (sm_103a) — round 17: 4 CTAs/SM VIA SMEM DIET
//   R11 (129.1us best) stored the A tile as [hi|hi|lo] -> hi duplicated.
//   Store segments separately (A_hi/A_lo/B_hi/B_lo, row stride 144B) and
//   reuse the A_hi ldmatrix fragment for both B_hi and B_lo products:
//   smem 67KB -> 55.4KB -> 4 CTAs/SM (16 warps) at ~constant instructions
//   (HMMA +20%, ldsm -20%). Everything else = R11 verbatim.
//   Gating branch dropped: softmax over batch sums to exactly 1.
// ---------------------------------------------------------------------------

#define BB   256
#define QQ   50
#define EE   50
#define DD   2000
#define NB   11
#define QB   (QQ * NB)        // 550
#define MT   128
#define NTILE 16
#define ROW2 144              // segment row stride bytes (72 bf16, K padded 50->64)
#define KS4  4                // 4 k-steps of 16 per segment
#define NT7  7                // q n-tiles (56 >= 50)

// smem layout (segments separate, no hi duplication)
#define SM_BH   0             // 56 * 144 = 8064
#define SM_BL   8064          // 8064  -> 16128
#define SM_AH   16128         // 128*144 = 18432 -> 34560
#define SM_AL   34560         // 18432 -> 52992
#define SM_HIST 52992         // 550*4 = 2200 -> 55192
#define SM_QV   55192         // 64 -> 55256
#define SM_DV   55256         // 128 -> 55384
#define SM_TOTAL 55424

__device__ unsigned char g_part[(size_t)NTILE * BB * QB];   // u8 slices

typedef unsigned long long u64;

__device__ __forceinline__ unsigned smem_u32(const void* p) {
    unsigned a;
    asm("{ .reg .u64 t; cvta.to.shared.u64 t, %1; cvt.u32.u64 %0, t; }"
        : "=r"(a) : "l"(p));
    return a;
}
__device__ __forceinline__ void split2(float x0, float x1,
                                       unsigned& hi, unsigned& lo) {
    __nv_bfloat16 h0 = __float2bfloat16(x0);
    __nv_bfloat16 h1 = __float2bfloat16(x1);
    float r0 = x0 - __bfloat162float(h0);
    float r1 = x1 - __bfloat162float(h1);
    __nv_bfloat16 l0 = __float2bfloat16(r0);
    __nv_bfloat16 l1 = __float2bfloat16(r1);
    hi = (unsigned)__bfloat16_as_ushort(h0) | ((unsigned)__bfloat16_as_ushort(h1) << 16);
    lo = (unsigned)__bfloat16_as_ushort(l0) | ((unsigned)__bfloat16_as_ushort(l1) << 16);
}
__device__ __forceinline__ void ldsm4(unsigned addr, unsigned& r0, unsigned& r1,
                                      unsigned& r2, unsigned& r3) {
    asm volatile("ldmatrix.sync.aligned.m8n8.x4.shared.b16 {%0,%1,%2,%3}, [%4];"
                 : "=r"(r0), "=r"(r1), "=r"(r2), "=r"(r3) : "r"(addr));
}
__device__ __forceinline__ void ldsm2(unsigned addr, unsigned& r0, unsigned& r1) {
    asm volatile("ldmatrix.sync.aligned.m8n8.x2.shared.b16 {%0,%1}, [%2];"
                 : "=r"(r0), "=r"(r1) : "r"(addr));
}
__device__ __forceinline__ void mma16816(float* c, const unsigned* a,
                                         unsigned b0, unsigned b1) {
    asm volatile(
        "mma.sync.aligned.m16n8k16.row.col.f32.bf16.bf16.f32 "
        "{%0,%1,%2,%3}, {%4,%5,%6,%7}, {%8,%9}, {%0,%1,%2,%3};"
        : "+f"(c[0]), "+f"(c[1]), "+f"(c[2]), "+f"(c[3])
        : "r"(a[0]), "r"(a[1]), "r"(a[2]), "r"(a[3]), "r"(b0), "r"(b1));
}

// ---------------------------------------------------------------------------
__global__ void __launch_bounds__(128, 4)
simhist_kernel(const float* __restrict__ qemb,
               const float* __restrict__ demb,
               const int*   __restrict__ qids,
               const int*   __restrict__ dids)
{
    extern __shared__ char smem[];
    const unsigned sbase = smem_u32(smem);
    const int b    = blockIdx.y;
    const int tile = blockIdx.x;
    const int tid  = threadIdx.x;
    const int lane = tid & 31;
    const int w    = tid >> 5;

    int* hist_s = (int*)(smem + SM_HIST);
    unsigned char* qv_s = (unsigned char*)(smem + SM_QV);
    unsigned char* dv_s = (unsigned char*)(smem + SM_DV);

    for (int i = tid; i < QB; i += 128) hist_s[i] = 0;

    // ---- build B segments (q side): rows 0..55 ----
    if (tid < 56) {
        unsigned* bh = (unsigned*)(smem + SM_BH + tid * ROW2);
        unsigned* bl = (unsigned*)(smem + SM_BL + tid * ROW2);
        if (tid < QQ) {
            const float2* src = (const float2*)(qemb + ((size_t)b * QQ + tid) * EE);
            float2 v[25];
            float ss = 0.f;
#pragma unroll
            for (int c = 0; c < 25; c++) { v[c] = src[c]; ss += v[c].x * v[c].x + v[c].y * v[c].y; }
            const float r = 1.0f / (sqrtf(ss) + 1e-8f);
            qv_s[tid] = (qids[b * QQ + tid] > 0) ? 1 : 0;
#pragma unroll
            for (int c = 0; c < 25; c++) {
                unsigned hi, lo;
                split2(v[c].x * r, v[c].y * r, hi, lo);
                bh[c] = hi;
                bl[c] = lo;
            }
#pragma unroll
            for (int j = 25; j < 36; j++) { bh[j] = 0; bl[j] = 0; }
        } else {
            qv_s[tid] = 0;
#pragma unroll
            for (int j = 0; j < 36; j++) { bh[j] = 0; bl[j] = 0; }
        }
    }

    // ---- build A segments (d side): each thread one row ----
    {
        const int gd  = tile * MT + tid;
        const bool ok = (gd < DD);
        const float2* src = (const float2*)(demb + ((size_t)b * DD + (ok ? gd : 0)) * EE);
        float2 v[25];
        float ss = 0.f;
#pragma unroll
        for (int c = 0; c < 25; c++) {
            float2 x = ok ? src[c] : make_float2(0.f, 0.f);
            v[c] = x;
            ss += x.x * x.x + x.y * x.y;
        }
        const float r = 1.0f / (sqrtf(ss) + 1e-8f);
        dv_s[tid] = (ok && dids[b * DD + (ok ? gd : 0)] > 0) ? 1 : 0;

        unsigned* ah = (unsigned*)(smem + SM_AH + tid * ROW2);
        unsigned* al = (unsigned*)(smem + SM_AL + tid * ROW2);
#pragma unroll
        for (int c = 0; c < 25; c++) {
            unsigned hi, lo;
            split2(v[c].x * r, v[c].y * r, hi, lo);
            ah[c] = hi;
            al[c] = lo;
        }
#pragma unroll
        for (int j = 25; j < 36; j++) { ah[j] = 0; al[j] = 0; }
    }
    __syncthreads();

    // ---- HMMA mainloop: 4 ksteps x {hi·hi, lo·hi, hi·lo} (A_hi frag reused) ----
    float acc[2][NT7][4];
#pragma unroll
    for (int mt = 0; mt < 2; mt++)
#pragma unroll
        for (int nt = 0; nt < NT7; nt++)
#pragma unroll
            for (int ci = 0; ci < 4; ci++) acc[mt][nt][ci] = 0.f;

    const unsigned aoff = (unsigned)(w * 32 + (lane & 15)) * ROW2
                        + (unsigned)((lane >> 4) * 16);
    const unsigned aAddrH = sbase + SM_AH + aoff;
    const unsigned aAddrL = sbase + SM_AL + aoff;
    const unsigned boff = (unsigned)((lane >> 4) * 8 + (lane & 7)) * ROW2
                        + (unsigned)(((lane >> 3) & 1) * 16);
    const unsigned boff2 = (unsigned)(48 + (lane & 7)) * ROW2
                         + (unsigned)(((lane >> 3) & 1) * 16);
    const unsigned bAddrH  = sbase + SM_BH + boff;
    const unsigned bAddr2H = sbase + SM_BH + boff2;
    const unsigned bAddrL  = sbase + SM_BL + boff;
    const unsigned bAddr2L = sbase + SM_BL + boff2;

#pragma unroll
    for (int ks = 0; ks < KS4; ks++) {
        unsigned aH[2][4], aL[2][4];
        ldsm4(aAddrH + ks * 32,              aH[0][0], aH[0][1], aH[0][2], aH[0][3]);
        ldsm4(aAddrH + 16 * ROW2 + ks * 32,  aH[1][0], aH[1][1], aH[1][2], aH[1][3]);
        ldsm4(aAddrL + ks * 32,              aL[0][0], aL[0][1], aL[0][2], aL[0][3]);
        ldsm4(aAddrL + 16 * ROW2 + ks * 32,  aL[1][0], aL[1][1], aL[1][2], aL[1][3]);

        unsigned bq[3][4], b6lo, b6hi;
#pragma unroll
        for (int p = 0; p < 3; p++)
            ldsm4(bAddrH + (unsigned)(p * 16 * ROW2) + ks * 32,
                  bq[p][0], bq[p][1], bq[p][2], bq[p][3]);
        ldsm2(bAddr2H + ks * 32, b6lo, b6hi);
        // hi_d · hi_q  and  lo_d · hi_q
#pragma unroll
        for (int mt = 0; mt < 2; mt++) {
#pragma unroll
            for (int p = 0; p < 3; p++) {
                mma16816(acc[mt][2 * p],     aH[mt], bq[p][0], bq[p][1]);
                mma16816(acc[mt][2 * p + 1], aH[mt], bq[p][2], bq[p][3]);
                mma16816(acc[mt][2 * p],     aL[mt], bq[p][0], bq[p][1]);
                mma16816(acc[mt][2 * p + 1], aL[mt], bq[p][2], bq[p][3]);
            }
            mma16816(acc[mt][6], aH[mt], b6lo, b6hi);
            mma16816(acc[mt][6], aL[mt], b6lo, b6hi);
        }
        // hi_d · lo_q (reuse aH fragments)
#pragma unroll
        for (int p = 0; p < 3; p++)
            ldsm4(bAddrL + (unsigned)(p * 16 * ROW2) + ks * 32,
                  bq[p][0], bq[p][1], bq[p][2], bq[p][3]);
        ldsm2(bAddr2L + ks * 32, b6lo, b6hi);
#pragma unroll
        for (int mt = 0; mt < 2; mt++) {
#pragma unroll
            for (int p = 0; p < 3; p++) {
                mma16816(acc[mt][2 * p],     aH[mt], bq[p][0], bq[p][1]);
                mma16816(acc[mt][2 * p + 1], aH[mt], bq[p][2], bq[p][3]);
            }
            mma16816(acc[mt][6], aH[mt], b6lo, b6hi);
        }
    }

    // ---- epilogue: 4-sample nibble hist + butterfly (R13-proven) ----
    const int r0 = w * 32 + (lane >> 2);
    const unsigned dvq = (unsigned)dv_s[r0]
                       | ((unsigned)dv_s[r0 + 8]  << 1)
                       | ((unsigned)dv_s[r0 + 16] << 2)
                       | ((unsigned)dv_s[r0 + 24] << 3);
    const int copyidx = lane >> 2;
    const int cbase   = (lane & 3) * 2;

#pragma unroll
    for (int nt = 0; nt < NT7; nt++) {
#pragma unroll
        for (int half = 0; half < 2; half++) {
            const int q = nt * 8 + cbase + half;
            u64 h = 0ull;
            {
                float s0 = acc[0][nt][half];
                float s1 = acc[0][nt][half + 2];
                float s2 = acc[1][nt][half];
                float s3 = acc[1][nt][half + 2];
                int c0 = min(max((int)fmaf(s0, 5.0f, 5.000005f), 0), NB - 1);
                int c1 = min(max((int)fmaf(s1, 5.0f, 5.000005f), 0), NB - 1);
                int c2 = min(max((int)fmaf(s2, 5.0f, 5.000005f), 0), NB - 1);
                int c3 = min(max((int)fmaf(s3, 5.0f, 5.000005f), 0), NB - 1);
                h += (u64)(dvq & 1u)        << (c0 * 4);
                h += (u64)((dvq >> 1) & 1u) << (c1 * 4);
                h += (u64)((dvq >> 2) & 1u) << (c2 * 4);
                h += (u64)((dvq >> 3) & 1u) << (c3 * 4);
            }
            u64 he = h & 0x0F0F0F0F0F0F0F0Full;
            u64 ho = (h >> 4) & 0x0F0F0F0F0F0F0F0Full;
#pragma unroll
            for (int o = 4; o < 32; o <<= 1) {
                he += __shfl_xor_sync(0xffffffffu, he, o);
                ho += __shfl_xor_sync(0xffffffffu, ho, o);
            }
            if (((nt * 2 + half) & 7) == copyidx && q < QQ && qv_s[q]) {
#pragma unroll
                for (int bin = 0; bin < NB; bin++) {
                    u64 src = (bin & 1) ? ho : he;
                    int cnt = (int)((src >> ((bin >> 1) * 8)) & 0xFFull);
                    if (cnt) atomicAdd(&hist_s[q * NB + bin], cnt);
                }
            }
        }
    }

    __syncthreads();
    unsigned char* dst = g_part + ((size_t)tile * BB + b) * QB;
    for (int i = tid; i < QB; i += 128) dst[i] = (unsigned char)hist_s[i];
}

// ---------------------------------------------------------------------------
// Reduce: out[b] = b1 + sum_i log(sum_tiles hist + 1e-5) * W1[i]
// ---------------------------------------------------------------------------
__global__ void reduce_kernel(const float* __restrict__ W1,
                              const float* __restrict__ b1,
                              float* __restrict__ out)
{
    const int b = blockIdx.x;
    const int t = threadIdx.x;
    float p = 0.f;
    for (int i = t; i < QB; i += 256) {
        int h = 0;
#pragma unroll
        for (int s = 0; s < NTILE; s++)
            h += (int)g_part[((size_t)s * BB + b) * QB + i];
        p += logf((float)h + 1e-5f) * W1[i];
    }
#pragma unroll
    for (int o = 16; o > 0; o >>= 1) p += __shfl_down_sync(0xffffffffu, p, o);

    __shared__ float red[8];
    if ((t & 31) == 0) red[t >> 5] = p;
    __syncthreads();
    if (t == 0) {
        float s = 0.f;
#pragma unroll
        for (int i = 0; i < 8; i++) s += red[i];
        out[b] = s + b1[0];
    }
}

// ---------------------------------------------------------------------------
extern "C" void kernel_launch(void* const* d_in, const int* in_sizes, int n_in,
                              void* d_out, int out_size)
{
    const float* qemb = (const float*)d_in[0];
    const float* demb = (const float*)d_in[1];
    const float* W1   = (const float*)d_in[2];
    const float* b1   = (const float*)d_in[3];
    const int*   qids = (const int*)d_in[5];
    const int*   dids = (const int*)d_in[6];
    for (int i = 0; i < n_in; i++) {
        switch (in_sizes[i]) {
            case BB * QQ * EE:  qemb = (const float*)d_in[i]; break;
            case BB * DD * EE:  demb = (const float*)d_in[i]; break;
            case QB:            W1   = (const float*)d_in[i]; break;
            case 1:             b1   = (const float*)d_in[i]; break;
            case BB * QQ:       qids = (const int*)d_in[i];   break;
            case BB * DD:       dids = (const int*)d_in[i];   break;
            default: break;     // Wg unused (softmax over batch sums to 1)
        }
    }
    float* out = (float*)d_out;

    static int smem_set = 0;
    if (!smem_set) {
        cudaFuncSetAttribute(simhist_kernel,
                             cudaFuncAttributeMaxDynamicSharedMemorySize, SM_TOTAL);
        smem_set = 1;
    }

    dim3 grid(NTILE, BB);                         // (16, 256) — single main launch
    simhist_kernel<<<grid, 128, SM_TOTAL>>>(qemb, demb, qids, dids);
    reduce_kernel<<<BB, 256>>>(W1, b1, out);
}